// round 1
// baseline (speedup 1.0000x reference)
#include <cuda_runtime.h>
#include <cuda_bf16.h>

// HPSS: S (2,2,1025,1024) fp32.
//   harm = median_31 along W (zero pad), perc = median_31 along H (zero pad)
//   mask_h = harm^2/(harm^2+perc^2), mask_p = perc^2/(harm^2+perc^2)  (MARGIN=1, POWER=2)
//   out[0:N) = S*mask_h ; out[N:2N) = S*mask_p
//
// Strategy: fused tiled kernel. Each thread computes two exact medians of 31
// via sorted forgetful selection (bitonic-16 + insert + 14 max-drop insertion
// passes), fully unrolled, register-resident, branch-free.

#define TILE_W 32
#define TILE_H 16
#define HALO   15
#define PATCH_W (TILE_W + 2 * HALO) // 62
#define PATCH_H (TILE_H + 2 * HALO) // 46
#define IMG_H 1025
#define IMG_W 1024
#define N_IMG 4

__device__ __forceinline__ float median31(const float* __restrict__ p, int stride) {
    float v[17];
#pragma unroll
    for (int i = 0; i < 16; i++) v[i] = p[i * stride];

    // Bitonic sort v[0..15] ascending (80 CE). All control is compile-time.
#pragma unroll
    for (int k = 2; k <= 16; k <<= 1) {
#pragma unroll
        for (int j = k >> 1; j > 0; j >>= 1) {
#pragma unroll
            for (int i = 0; i < 16; i++) {
                int l = i ^ j;
                if (l > i) {
                    float a = v[i], b = v[l];
                    float mn = fminf(a, b);
                    float mx = fmaxf(a, b);
                    if ((i & k) == 0) { v[i] = mn; v[l] = mx; }
                    else              { v[i] = mx; v[l] = mn; }
                }
            }
        }
    }

    // Insert 17th element: bubble down (16 CE) -> v[0..16] sorted ascending.
    v[16] = p[16 * stride];
#pragma unroll
    for (int i = 15; i >= 0; i--) {
        float a = v[i], b = v[i + 1];
        v[i]     = fminf(a, b);
        v[i + 1] = fmaxf(a, b);
    }

    // Forgetful stages: at stage s (n = 17+s), active sorted set is v[s..16].
    // Drop min v[s] (implicit), merge-insert new element while carrying the
    // max out of the set. Buffer sizes 17,16,...,4; final active = v[14..16].
#pragma unroll
    for (int n = 17; n < 31; n++) {
        float t = p[n * stride];
#pragma unroll
        for (int i = n - 16; i <= 16; i++) {
            float lo = fminf(v[i], t);
            t        = fmaxf(v[i], t);
            v[i] = lo;
        }
    }
    return v[15]; // middle of final sorted triple v[14..16]
}

__global__ __launch_bounds__(TILE_W * TILE_H)
void hpss_kernel(const float* __restrict__ S, float* __restrict__ out) {
    __shared__ float patch[PATCH_H][PATCH_W];

    const int bx  = blockIdx.x * TILE_W;
    const int by  = blockIdx.y * TILE_H;
    const int img = blockIdx.z;
    const float* __restrict__ Simg = S + (size_t)img * IMG_H * IMG_W;

    // Cooperative patch load with zero padding outside the image.
    const int tid = threadIdx.y * TILE_W + threadIdx.x;
#pragma unroll 2
    for (int idx = tid; idx < PATCH_H * PATCH_W; idx += TILE_W * TILE_H) {
        int r = idx / PATCH_W;
        int c = idx - r * PATCH_W;
        int gh = by + r - HALO;
        int gw = bx + c - HALO;
        float val = 0.0f;
        if (gh >= 0 && gh < IMG_H && gw >= 0 && gw < IMG_W)
            val = Simg[gh * IMG_W + gw];
        patch[r][c] = val;
    }
    __syncthreads();

    const int h = by + threadIdx.y;
    const int w = bx + threadIdx.x;
    if (h >= IMG_H) return;

    // harm: window along W at row (ty+HALO), cols tx..tx+30 (center tx+HALO)
    float harm = median31(&patch[threadIdx.y + HALO][threadIdx.x], 1);
    // perc: window along H at col (tx+HALO), rows ty..ty+30
    float perc = median31(&patch[threadIdx.y][threadIdx.x + HALO], PATCH_W);

    const float s = patch[threadIdx.y + HALO][threadIdx.x + HALO];

    const float tiny = 1.17549435e-38f; // finfo(float32).tiny
    float Z = fmaxf(harm, perc);
    if (Z < tiny) Z = 1.0f;
    float hn = harm / Z;
    float pn = perc / Z;
    float m = hn * hn;
    float r = pn * pn;
    float inv = 1.0f / (m + r);

    size_t o = (size_t)img * (IMG_H * IMG_W) + (size_t)h * IMG_W + w;
    const size_t plane = (size_t)N_IMG * IMG_H * IMG_W;
    out[o]         = s * (m * inv);
    out[o + plane] = s * (r * inv);
}

extern "C" void kernel_launch(void* const* d_in, const int* in_sizes, int n_in,
                              void* d_out, int out_size) {
    const float* S = (const float*)d_in[0];
    float* out = (float*)d_out;
    (void)in_sizes; (void)n_in; (void)out_size;

    dim3 block(TILE_W, TILE_H);
    dim3 grid(IMG_W / TILE_W, (IMG_H + TILE_H - 1) / TILE_H, N_IMG);
    hpss_kernel<<<grid, block>>>(S, out);
}

// round 4
// speedup vs baseline: 1.5669x; 1.5669x over previous
#include <cuda_runtime.h>
#include <cuda_bf16.h>

// HPSS: S (2,2,1025,1024) fp32.
//   harm = median_31 along W (zero pad), perc = median_31 along H (zero pad)
//   mask_h = harm^2/(harm^2+perc^2), mask_p = perc^2/(harm^2+perc^2)
//   out[0:N) = S*mask_h ; out[N:2N) = S*mask_p
//
// R2: shared-base forgetful selection. 16 consecutive outputs along the filter
// axis share a sorted 16-element window intersection; each output then inserts
// its 15 private elements through a narrowing (16->1) min/max carry chain.
// 240 FMNMX per median (+10 amortized sort) vs 458 for standalone selection.

#define IMG_H 1025
#define IMG_W 1024
#define N_IMG 4
#define HALO  15

#define TILE_W 64
#define TILE_H 32
#define PATCH_H (TILE_H + 2 * HALO)   // 62
#define PATCH_W (TILE_W + 2 * HALO)   // 94
#define PITCH   (PATCH_W + 1)         // 95 (odd -> conflict-free column access)
#define NTHREADS 128

__device__ __forceinline__ void sort16(float v[16]) {
#pragma unroll
    for (int k = 2; k <= 16; k <<= 1) {
#pragma unroll
        for (int j = k >> 1; j > 0; j >>= 1) {
#pragma unroll
            for (int i = 0; i < 16; i++) {
                int l = i ^ j;
                if (l > i) {
                    float a = v[i], b = v[l];
                    float mn = fminf(a, b);
                    float mx = fmaxf(a, b);
                    if ((i & k) == 0) { v[i] = mn; v[l] = mx; }
                    else              { v[i] = mx; v[l] = mn; }
                }
            }
        }
    }
}

// Median of 31 = sorted base b[16] (window intersection, element offsets
// 15..30 of the window union) + 15 private elements at union offsets
// [i, i+14] mapped as: off = (i+k < 15+i ... ) -> below part [i..14], above
// part [31..30+i]. q points at union offset 0; STRIDE in floats.
template<int STRIDE>
__device__ __forceinline__ float med31_from_base(const float b[16],
                                                 const float* __restrict__ q,
                                                 int i) {
    float w[15];
    // insertion 0: buffer 16 -> keep 15 (drop overall min and max)
    {
        float t = q[((0 < 15 - i) ? (i + 0) : (16 + i + 0)) * STRIDE];
        t = fmaxf(b[0], t);
#pragma unroll
        for (int j = 1; j <= 14; j++) {
            w[j - 1] = fminf(b[j], t);
            t        = fmaxf(b[j], t);
        }
        w[14] = fminf(b[15], t);
    }
    // insertions k = 1..14: buffer B = 16-k shrinks to 1
#pragma unroll
    for (int k = 1; k <= 14; k++) {
        const int B = 16 - k;
        float u = q[((k < 15 - i) ? (i + k) : (16 + i + k)) * STRIDE];
        u = fmaxf(w[0], u);
#pragma unroll
        for (int j = 1; j <= B - 2; j++) {
            float lo = fminf(w[j], u);
            u        = fmaxf(w[j], u);
            w[j - 1] = lo;
        }
        w[B - 2] = fminf(w[B - 1], u);
    }
    return w[0];
}

__global__ __launch_bounds__(NTHREADS)
void hpss_kernel(const float* __restrict__ S, float* __restrict__ out) {
    __shared__ float patch[PATCH_H][PITCH];
    __shared__ float harm[TILE_H][TILE_W + 1];

    const int bx  = blockIdx.x * TILE_W;
    const int by  = blockIdx.y * TILE_H;
    const int img = blockIdx.z;
    const float* __restrict__ Simg = S + (size_t)img * IMG_H * IMG_W;

    const int tid = threadIdx.x;

    // Cooperative patch load with zero padding.
#pragma unroll 4
    for (int idx = tid; idx < PATCH_H * PATCH_W; idx += NTHREADS) {
        int r = idx / PATCH_W;
        int c = idx - r * PATCH_W;
        int gh = by + r - HALO;
        int gw = bx + c - HALO;
        float val = 0.0f;
        if (gh >= 0 && gh < IMG_H && gw >= 0 && gw < IMG_W)
            val = Simg[gh * IMG_W + gw];
        patch[r][c] = val;
    }
    __syncthreads();

    // ---- Phase A: horizontal medians (harm), thread owns a 16-wide row run
    {
        const int row = tid & 31;       // 0..31
        const int g   = tid >> 5;       // 0..3 -> cols g*16..g*16+15
        const int c0  = g * 16;
        const float* __restrict__ prow = &patch[row + HALO][c0];

        float b[16];
#pragma unroll
        for (int j = 0; j < 16; j++) b[j] = prow[15 + j];
        sort16(b);

#pragma unroll
        for (int i = 0; i < 16; i++)
            harm[row][c0 + i] = med31_from_base<1>(b, prow, i);
    }
    __syncthreads();

    // ---- Phase B: vertical medians (perc), thread owns a 16-tall col run;
    //      combine with harm + S and write both output planes.
    {
        const int col = tid & 63;       // 0..63
        const int gy  = tid >> 6;       // 0..1 -> rows gy*16..gy*16+15
        const int r0  = gy * 16;
        const float* __restrict__ pcol = &patch[r0][col + HALO];

        float b[16];
#pragma unroll
        for (int j = 0; j < 16; j++) b[j] = pcol[(15 + j) * PITCH];
        sort16(b);

        const size_t plane = (size_t)N_IMG * IMG_H * IMG_W;

#pragma unroll
        for (int i = 0; i < 16; i++) {
            float p = med31_from_base<PITCH>(b, pcol, i);

            int h_local = r0 + i;
            int gh = by + h_local;
            if (gh < IMG_H) {
                float hmed = harm[h_local][col];
                float s    = patch[h_local + HALO][col + HALO];

                float hh = hmed * hmed;
                float pp = p * p;
                float inv = 1.0f / (hh + pp);

                size_t o = (size_t)img * (IMG_H * IMG_W) + (size_t)gh * IMG_W
                         + (bx + col);
                out[o]         = s * (hh * inv);
                out[o + plane] = s * (pp * inv);
            }
        }
    }
}

extern "C" void kernel_launch(void* const* d_in, const int* in_sizes, int n_in,
                              void* d_out, int out_size) {
    const float* S = (const float*)d_in[0];
    float* out = (float*)d_out;
    (void)in_sizes; (void)n_in; (void)out_size;

    dim3 block(NTHREADS);
    dim3 grid(IMG_W / TILE_W, (IMG_H + TILE_H - 1) / TILE_H, N_IMG);
    hpss_kernel<<<grid, block>>>(S, out);
}

// round 6
// speedup vs baseline: 3.2860x; 2.0971x over previous
#include <cuda_runtime.h>
#include <math_constants.h>

// HPSS: S (2,2,1025,1024) fp32.
//   harm = median_31 along W (zero pad), perc = median_31 along H (zero pad)
//   mask_h = harm^2/(harm^2+perc^2), mask_p = perc^2/(harm^2+perc^2)
//   out[0:N) = S*mask_h ; out[N:2N) = S*mask_p
//
// R6: shared sorted base (positional window intersection, valid for all 16
// outputs of a run) + incrementally maintained sorted private set P (15
// elements). Per output: delete one known value (compare+select shift),
// insert one value (min/max carry chain), then rank-15 select of
// P(15 sorted) u base(16 sorted) via min_j max(P[j-1], b[15-j]).
// ~106 alu ops per median vs ~250 in R4.

#define IMG_H 1025
#define IMG_W 1024
#define N_IMG 4
#define HALO  15

#define TILE_W 64
#define TILE_H 32
#define PATCH_H (TILE_H + 2 * HALO)   // 62
#define PATCH_W (TILE_W + 2 * HALO)   // 94
#define PITCH   (PATCH_W + 1)         // 95 (odd -> conflict-free column access)
#define NTHREADS 128

__device__ __forceinline__ void sort16(float v[16]) {
#pragma unroll
    for (int k = 2; k <= 16; k <<= 1) {
#pragma unroll
        for (int j = k >> 1; j > 0; j >>= 1) {
#pragma unroll
            for (int i = 0; i < 16; i++) {
                int l = i ^ j;
                if (l > i) {
                    float a = v[i], b = v[l];
                    float mn = fminf(a, b);
                    float mx = fmaxf(a, b);
                    if ((i & k) == 0) { v[i] = mn; v[l] = mx; }
                    else              { v[i] = mx; v[l] = mn; }
                }
            }
        }
    }
}

// Rank-15 (0-indexed; 16th smallest) of sorted P[0..14] u sorted b[0..15].
__device__ __forceinline__ float sel16th(const float P[16], const float b[16]) {
    float c[16];
    c[0] = b[15];
#pragma unroll
    for (int j = 1; j <= 15; j++) c[j] = fmaxf(P[j - 1], b[15 - j]);
#pragma unroll
    for (int s = 8; s >= 1; s >>= 1)
#pragma unroll
        for (int j = 0; j < s; j++) c[j] = fminf(c[j], c[j + s]);
    return c[0];
}

// Replace value v (present in sorted P[0..14]) with value u, restoring sorted
// order. P[15] stays +INF.
__device__ __forceinline__ void replace_sorted(float P[16], float v, float u) {
    float w[14];
#pragma unroll
    for (int j = 0; j < 14; j++)
        w[j] = (P[j] < v) ? P[j] : P[j + 1];   // delete first occurrence of v
    float t = u;                                // insert u via min/max carry
#pragma unroll
    for (int j = 0; j < 14; j++) {
        float lo = fminf(w[j], t);
        t        = fmaxf(w[j], t);
        P[j] = lo;
    }
    P[14] = t;
}

__global__ __launch_bounds__(NTHREADS)
void hpss_kernel(const float* __restrict__ S, float* __restrict__ out) {
    __shared__ float patch[PATCH_H][PITCH];
    __shared__ float harm[TILE_H][TILE_W + 1];

    const int bx  = blockIdx.x * TILE_W;
    const int by  = blockIdx.y * TILE_H;
    const int img = blockIdx.z;
    const float* __restrict__ Simg = S + (size_t)img * IMG_H * IMG_W;

    const int tid = threadIdx.x;

    // Cooperative patch load with zero padding.
#pragma unroll 4
    for (int idx = tid; idx < PATCH_H * PATCH_W; idx += NTHREADS) {
        int r = idx / PATCH_W;
        int c = idx - r * PATCH_W;
        int gh = by + r - HALO;
        int gw = bx + c - HALO;
        float val = 0.0f;
        if (gh >= 0 && gh < IMG_H && gw >= 0 && gw < IMG_W)
            val = Simg[gh * IMG_W + gw];
        patch[r][c] = val;
    }
    __syncthreads();

    // ---- Phase A: horizontal medians (harm); thread owns a 16-wide row run.
    {
        const int row = tid & 31;       // 0..31
        const int g   = tid >> 5;       // 0..3 -> cols g*16..g*16+15
        const int c0  = g * 16;
        const float* __restrict__ q = &patch[row + HALO][c0];

        float b[16], P[16];
#pragma unroll
        for (int j = 0; j < 16; j++) b[j] = q[15 + j];
        sort16(b);

#pragma unroll
        for (int j = 0; j < 15; j++) P[j] = q[j];   // L = positions 0..14
        P[15] = CUDART_INF_F;
        sort16(P);                                   // INF stays at P[15]

#pragma unroll
        for (int i = 0; i < 16; i++) {
            if (i > 0)
                replace_sorted(P, q[i - 1], q[31 + i - 1]); // drop L[i-1], add R[i-1]
            harm[row][c0 + i] = sel16th(P, b);
        }
    }
    __syncthreads();

    // ---- Phase B: vertical medians (perc); thread owns a 16-tall col run;
    //      combine with harm + S, write both output planes.
    {
        const int col = tid & 63;       // 0..63
        const int gy  = tid >> 6;       // 0..1 -> rows gy*16..gy*16+15
        const int r0  = gy * 16;
        const float* __restrict__ q = &patch[r0][col + HALO];

        float b[16], P[16];
#pragma unroll
        for (int j = 0; j < 16; j++) b[j] = q[(15 + j) * PITCH];
        sort16(b);

#pragma unroll
        for (int j = 0; j < 15; j++) P[j] = q[j * PITCH];
        P[15] = CUDART_INF_F;
        sort16(P);

        const size_t plane = (size_t)N_IMG * IMG_H * IMG_W;

#pragma unroll
        for (int i = 0; i < 16; i++) {
            if (i > 0)
                replace_sorted(P, q[(i - 1) * PITCH], q[(31 + i - 1) * PITCH]);
            float p = sel16th(P, b);

            int h_local = r0 + i;
            int gh = by + h_local;
            if (gh < IMG_H) {
                float hmed = harm[h_local][col];
                float s    = patch[h_local + HALO][col + HALO];

                float hh = hmed * hmed;
                float pp = p * p;
                float inv = 1.0f / (hh + pp);

                size_t o = (size_t)img * (IMG_H * IMG_W) + (size_t)gh * IMG_W
                         + (bx + col);
                out[o]         = s * (hh * inv);
                out[o + plane] = s * (pp * inv);
            }
        }
    }
}

extern "C" void kernel_launch(void* const* d_in, const int* in_sizes, int n_in,
                              void* d_out, int out_size) {
    const float* S = (const float*)d_in[0];
    float* out = (float*)d_out;
    (void)in_sizes; (void)n_in; (void)out_size;

    dim3 block(NTHREADS);
    dim3 grid(IMG_W / TILE_W, (IMG_H + TILE_H - 1) / TILE_H, N_IMG);
    hpss_kernel<<<grid, block>>>(S, out);
}